// round 6
// baseline (speedup 1.0000x reference)
#include <cuda_runtime.h>
#include <cuda_bf16.h>
#include <cstdint>

#define NN   256
#define NE   1024
#define MAXC 64
#define WINF (1<<20)
#define NT   256       // threads per block

typedef unsigned long long ull;
union F2U { float2 f; ull u; };

// ---------------- resettable state (ONE memset per replay) ----------------
struct __align__(16) Flags {
    float hidden[128 * 200];   // FC1 atomic accumulators (needs zero)
    int   done[NN * 64];       // (neuron, batch-pair) completion flags
    int   hcnt[2];             // FC1 chunk-task counters per 64-batch half
    int   sched_ready;
};
__device__ Flags g_flags;

// ---------------- persistent scratch (rewritten before use) ----------------
__device__ float g_act[(size_t)NN * 128 * 784];   // [n][b][p]
__device__ int   g_fin[NN * MAXC];
__device__ int   g_fcc[NN * MAXC];
__device__ int   g_fdeg[NN];
__device__ int   g_order[NN];
__device__ int   g_ntasks;
__device__ int   g_gsz, g_ncg, g_fc1target;       // FC1 chunk grouping

#define FMA2(d, a, b) \
    asm("fma.rn.f32x2 %0, %1, %2, %0;" : "+l"(d) : "l"(a), "l"(b))

__device__ __forceinline__ int ldacq(const int* p) {
    int v; asm volatile("ld.acquire.gpu.global.b32 %0, [%1];" : "=r"(v) : "l"(p) : "memory");
    return v;
}
__device__ __forceinline__ void spinf(const int* p) {
    if (ldacq(p)) return;
    while (!ldacq(p)) __nanosleep(20);
}

// ---------------- shared memory union ----------------
struct SchedSM { int src[NE], tgt[NE], wave[NN], need[NN], list[NN]; int chg, cnt; };
struct ConvSM  { ull img[2][1056]; ull wk2[18 * 25]; };   // 32 rows x 33 ull (2 batches packed)
struct FCSM    { float w[16][72]; float2 a[16][66]; };
union  SMU { SchedSM sch; ConvSM cv; FCSM fc; };

// stage one channel (2 batches packed in ull) — conflict-free STS.64
__device__ __forceinline__ void stage2(ull* imgU, const float* sp, int tid) {
    if (tid < 196) {
        const int col  = tid % 28;
        const int rowg = tid / 28;
        const float* p0 = sp + rowg * 4 * 28 + col;
        const float* p1 = p0 + 784;
        ull* d = imgU + (rowg * 4 + 2) * 33 + col + 2;
#pragma unroll
        for (int r = 0; r < 4; ++r) {
            F2U u; u.f = make_float2(__ldg(p0 + r * 28), __ldg(p1 + r * 28));
            d[r * 33] = u.u;
        }
    }
}

// 4px x 2batch packed conv
__device__ __forceinline__ void conv4(const ull* imb, const ull* w2, ull acc[4]) {
#pragma unroll
    for (int dy = 0; dy < 5; ++dy) {
        const ull* rp = imb + dy * 33;
        ull v[8];
#pragma unroll
        for (int j = 0; j < 8; ++j) v[j] = rp[j];
#pragma unroll
        for (int dx = 0; dx < 5; ++dx) {
            ull wv = w2[dy * 5 + dx];
#pragma unroll
            for (int o = 0; o < 4; ++o) FMA2(acc[o], wv, v[dx + o]);
        }
    }
}

__device__ __forceinline__ void store4(ull acc[4], float* d0) {
    F2U u0, u1, u2, u3;
    u0.u = acc[0]; u1.u = acc[1]; u2.u = acc[2]; u3.u = acc[3];
    float4 o0 = make_float4(fmaxf(u0.f.x, 0.f), fmaxf(u1.f.x, 0.f),
                            fmaxf(u2.f.x, 0.f), fmaxf(u3.f.x, 0.f));
    float4 o1 = make_float4(fmaxf(u0.f.y, 0.f), fmaxf(u1.f.y, 0.f),
                            fmaxf(u2.f.y, 0.f), fmaxf(u3.f.y, 0.f));
    *(float4*)d0         = o0;
    *(float4*)(d0 + 784) = o1;
}

// =====================================================================
// single persistent kernel
// =====================================================================
__global__ void __launch_bounds__(NT) net_kernel(
    const float* __restrict__ x,
    const int* __restrict__ src, const int* __restrict__ tgt,
    const float* __restrict__ conv_w, const float* __restrict__ conv_b,
    const float* __restrict__ fc1_w,  const float* __restrict__ fc1_b,
    const float* __restrict__ fc2_w,  const float* __restrict__ fc2_b,
    float* __restrict__ out, int cmax, int fcK, int nb)
{
    __shared__ SMU sm;
    const int tid = threadIdx.x;
    const int bid = blockIdx.x;

    // ================= block 0: scheduler only =================
    if (bid == 0) {
        for (int i = tid; i < NE; i += NT) { sm.sch.src[i] = src[i]; sm.sch.tgt[i] = tgt[i]; }
        for (int i = tid; i < NN; i += NT) { sm.sch.wave[i] = (i == 0) ? 0 : WINF; sm.sch.need[i] = 0; }
        if (tid == 0) { sm.sch.chg = 0; sm.sch.cnt = 0; }
        __syncthreads();

        for (int pass = 0; pass < 300; ++pass) {
            for (int e = tid; e < NE; e += NT) {
                int ws = sm.sch.wave[sm.sch.src[e]];
                if (ws + 1 < sm.sch.wave[sm.sch.tgt[e]]) {
                    atomicMin(&sm.sch.wave[sm.sch.tgt[e]], ws + 1); sm.sch.chg = 1;
                }
            }
            __syncthreads();
            int c = sm.sch.chg; __syncthreads();
            if (tid == 0) sm.sch.chg = 0;
            __syncthreads();
            if (!c) break;
        }

        if (tid == 0) sm.sch.need[255] = 1;
        __syncthreads();
        for (int pass = 0; pass < 300; ++pass) {
            for (int e = tid; e < NE; e += NT) {
                int s = sm.sch.src[e], t = sm.sch.tgt[e];
                if (sm.sch.need[t] && sm.sch.wave[s] < sm.sch.wave[t] && !sm.sch.need[s]) {
                    sm.sch.need[s] = 1; sm.sch.chg = 1;
                }
            }
            __syncthreads();
            int c = sm.sch.chg; __syncthreads();
            if (tid == 0) sm.sch.chg = 0;
            __syncthreads();
            if (!c) break;
        }

        for (int n = tid; n < NN; n += NT) {
            if (n != 0 && n != 255 && sm.sch.need[n]) {
                int r = 0;
                for (int m = 1; m < NN - 1; ++m)
                    if (sm.sch.need[m] && (sm.sch.wave[m] < sm.sch.wave[n] ||
                        (sm.sch.wave[m] == sm.sch.wave[n] && m < n))) r++;
                sm.sch.list[r] = n;
                atomicAdd(&sm.sch.cnt, 1);
            }
        }
        __syncthreads();
        const int total = sm.sch.cnt;

        {   // filtered in-lists via warp ballots (fcc = original channel rank)
            const int w8 = tid >> 5, lane = tid & 31;
            for (int ni = w8; ni <= total; ni += 8) {
                int n  = (ni == total) ? 255 : sm.sch.list[ni];
                int wn = sm.sch.wave[n];
                int cbase = 0, cnt = 0;
                for (int ch = 0; ch < NE; ch += 32) {
                    int e = ch + lane;
                    int te = sm.sch.tgt[e], se = sm.sch.src[e];
                    unsigned m_all  = __ballot_sync(0xffffffffu, te == n);
                    unsigned m_keep = __ballot_sync(0xffffffffu, te == n && sm.sch.wave[se] < wn);
                    if (m_keep & (1u << lane)) {
                        int c   = cbase + __popc(m_all  & ((1u << lane) - 1));
                        int pos = cnt   + __popc(m_keep & ((1u << lane) - 1));
                        if (pos < MAXC) { g_fin[n * MAXC + pos] = se; g_fcc[n * MAXC + pos] = c; }
                    }
                    cbase += __popc(m_all);
                    cnt   += __popc(m_keep);
                }
                if (lane == 0) g_fdeg[n] = cnt < MAXC ? cnt : MAXC;
            }
        }
        __syncthreads();

        // sort each in-list by (input wave, original rank): late producers last
        for (int idx = tid; idx <= total; idx += NT) {
            int n = (idx == total) ? 255 : sm.sch.list[idx];
            int C = g_fdeg[n];
            int* fi = g_fin + n * MAXC;
            int* fo = g_fcc + n * MAXC;
            for (int i = 0; i < C - 1; ++i) {
                int best = i, bk = sm.sch.wave[fi[i]] * 4096 + fo[i];
                for (int j = i + 1; j < C; ++j) {
                    int k = sm.sch.wave[fi[j]] * 4096 + fo[j];
                    if (k < bk) { bk = k; best = j; }
                }
                if (best != i) {
                    int a = fi[i]; fi[i] = fi[best]; fi[best] = a;
                    int b = fo[i]; fo[i] = fo[best]; fo[best] = b;
                }
            }
        }
        for (int i = tid; i < total; i += NT) g_order[i] = sm.sch.list[i];
        __syncthreads();
        if (tid == 0) {
            g_ntasks = total * 64;
            int Kc  = g_fdeg[255] * 49;
            int G   = (Kc + 255) >> 8;  if (G < 1) G = 1;
            int NCG = (Kc + G - 1) / G;
            g_gsz = G; g_ncg = NCG; g_fc1target = 4 * NCG;
            __threadfence();
            *(volatile int*)&g_flags.sched_ready = 1;
        }
        return;
    }

    // ================= worker blocks =================
    for (int i = tid; i < 2 * 1056; i += NT) ((ull*)sm.cv.img)[i] = 0ull;
    const int yy  = tid / 7;           // valid for tid<196
    const int xx0 = (tid % 7) * 4;
    __syncthreads();

    // ---- wave 0: neuron 0 from x ----
    {
        if (tid < 25) { F2U u; float w = conv_w[tid]; u.f = make_float2(w, w); sm.cv.wk2[tid] = u.u; }
        const float bias = conv_b[0];
        for (int t = bid - 1; t < 64; t += nb - 1) {
            stage2(sm.cv.img[0], x + (size_t)t * 1568, tid);
            __syncthreads();
            if (tid < 196) {
                ull acc[4];
                F2U b2; b2.f = make_float2(bias, bias);
#pragma unroll
                for (int o = 0; o < 4; ++o) acc[o] = b2.u;
                conv4(sm.cv.img[0] + yy * 33 + xx0, sm.cv.wk2, acc);
                store4(acc, g_act + (size_t)(t * 2) * 784 + yy * 28 + xx0);
            }
            __syncthreads();
            if (tid == 0) {
                __threadfence();
                *(volatile int*)&g_flags.done[t] = 1;
            }
        }
    }

    // ---- wait for schedule ----
    spinf(&g_flags.sched_ready);
    __syncthreads();

    const int ntasks  = g_ntasks;
    const int fdeg255 = g_fdeg[255];

    // ---- dataflow conv tasks (inputs sorted by wave; JIT per-channel gate) ----
    for (int t = bid - 1; t < ntasks; t += nb - 1) {
        const int ni = t >> 6;
        const int pb = t & 63;
        const int n  = g_order[ni];
        const int C  = g_fdeg[n];
        const int* fin = g_fin + n * MAXC;
        const int* fcc = g_fcc + n * MAXC;
        const float* wbase = conv_w + (size_t)n * cmax * 25;

        const int CW = C < 16 ? C : 16;
        for (int i = tid; i < CW * 25; i += NT) {      // weight prefetch (dep-free)
            int c = i / 25, r = i - c * 25;
            F2U u; float w = wbase[fcc[c] * 25 + r];
            u.f = make_float2(w, w);
            sm.cv.wk2[c * 25 + r] = u.u;
        }

        spinf(&g_flags.done[fin[0] * 64 + pb]);        // earliest producer first
        stage2(sm.cv.img[0], g_act + ((size_t)fin[0] * 128 + pb * 2) * 784, tid);
        __syncthreads();

        ull acc[4];
        { F2U b2; float b = conv_b[n]; b2.f = make_float2(b, b);
#pragma unroll
          for (int o = 0; o < 4; ++o) acc[o] = b2.u; }

        for (int c = 0; c < C; ++c) {
            const int buf = c & 1;
            if (c + 1 < C) {
                spinf(&g_flags.done[fin[c + 1] * 64 + pb]);   // JIT gate
                stage2(sm.cv.img[buf ^ 1],
                       g_act + ((size_t)fin[c + 1] * 128 + pb * 2) * 784, tid);
                if (c + 1 >= 16 && tid < 25) {
                    F2U u; float w = wbase[fcc[c + 1] * 25 + tid];
                    u.f = make_float2(w, w);
                    sm.cv.wk2[(16 + ((c + 1) & 1)) * 25 + tid] = u.u;
                }
            }
            if (tid < 196) {
                const ull* w2 = sm.cv.wk2 + ((c < 16) ? c : (16 + (c & 1))) * 25;
                conv4(sm.cv.img[buf] + yy * 33 + xx0, w2, acc);
            }
            __syncthreads();
        }
        if (tid < 196)
            store4(acc, g_act + ((size_t)n * 128 + pb * 2) * 784 + yy * 28 + xx0);
        __syncthreads();
        if (tid == 0) {
            __threadfence();
            *(volatile int*)&g_flags.done[n * 64 + pb] = 1;
        }
    }

    // ---- FC1 chunk tasks: (tile 64h x 64b) x k-chunk-group, gated per input ----
    {
        const int G   = g_gsz;
        const int NCG = g_ncg;
        const int Kc  = fdeg255 * 49;
        const int* fin = g_fin + 255 * MAXC;
        const int* fcc = g_fcc + 255 * MAXC;
        const int hg = tid >> 5;         // 8 groups of 8 h
        const int bg = tid & 31;         // 32 groups of 2 b

        for (int t = bid - 1; t < 8 * NCG; t += nb - 1) {
            const int tile = t / NCG;
            const int cg   = t - tile * NCG;
            const int h0   = (tile >> 1) * 64;
            const int b0   = (tile & 1) * 64;
            const int kq1  = min(cg * G + G, Kc);

            ull acc[4][2];
#pragma unroll
            for (int i = 0; i < 4; ++i) { acc[i][0] = 0ull; acc[i][1] = 0ull; }

            int lastc = -1;
            for (int kq = cg * G; kq < kq1; ++kq) {
                const int c  = kq / 49;
                const int p0 = (kq - c * 49) * 16;
                if (c != lastc) {   // gate only on THIS input's 32 pbs of this half
                    if (tid < 32) spinf(&g_flags.done[fin[c] * 64 + (b0 >> 1) + tid]);
                    __syncthreads();
                    lastc = c;
                }
                const float* wrow = fc1_w + (size_t)fcc[c] * 784 + p0;
                const float* arow = g_act + ((size_t)fin[c] * 128 + b0) * 784 + p0;
                // stage weights 64h x 16k
                {
                    int row = tid >> 2, c4 = tid & 3;
                    int h = h0 + row;
                    float4 v = (h < 200) ? *(const float4*)(wrow + (size_t)h * fcK + c4 * 4)
                                         : make_float4(0.f, 0.f, 0.f, 0.f);
                    sm.fc.w[c4 * 4 + 0][row] = v.x; sm.fc.w[c4 * 4 + 1][row] = v.y;
                    sm.fc.w[c4 * 4 + 2][row] = v.z; sm.fc.w[c4 * 4 + 3][row] = v.w;
                }
                // stage acts 64b x 16k (dup-packed)
                {
                    int row = tid >> 2, c4 = tid & 3;
                    float4 v = *(const float4*)(arow + (size_t)row * 784 + c4 * 4);
                    sm.fc.a[c4 * 4 + 0][row] = make_float2(v.x, v.x);
                    sm.fc.a[c4 * 4 + 1][row] = make_float2(v.y, v.y);
                    sm.fc.a[c4 * 4 + 2][row] = make_float2(v.z, v.z);
                    sm.fc.a[c4 * 4 + 3][row] = make_float2(v.w, v.w);
                }
                __syncthreads();
#pragma unroll
                for (int k = 0; k < 16; ++k) {
                    const ull* wp = (const ull*)&sm.fc.w[k][hg * 8];
                    const ull* ap = (const ull*)&sm.fc.a[k][bg * 2];
                    ull w0 = wp[0], w1 = wp[1], w2v = wp[2], w3 = wp[3];
                    ull a0 = ap[0], a1 = ap[1];
                    FMA2(acc[0][0], w0,  a0); FMA2(acc[0][1], w0,  a1);
                    FMA2(acc[1][0], w1,  a0); FMA2(acc[1][1], w1,  a1);
                    FMA2(acc[2][0], w2v, a0); FMA2(acc[2][1], w2v, a1);
                    FMA2(acc[3][0], w3,  a0); FMA2(acc[3][1], w3,  a1);
                }
                __syncthreads();
            }
#pragma unroll
            for (int i = 0; i < 4; ++i) {
                const int h = h0 + hg * 8 + i * 2;
                if (h < 200) {
#pragma unroll
                    for (int j = 0; j < 2; ++j) {
                        F2U u; u.u = acc[i][j];
                        const int b = b0 + bg * 2 + j;
                        atomicAdd(&g_flags.hidden[b * 200 + h],     u.f.x);
                        atomicAdd(&g_flags.hidden[b * 200 + h + 1], u.f.y);
                    }
                }
            }
            __threadfence();
            __syncthreads();
            if (tid == 0) atomicAdd(&g_flags.hcnt[b0 >> 6], 1);
        }
    }

    // ---- FC2 + log_softmax: warp tasks ----
    {
        const int lane   = tid & 31;
        const int gw     = (bid - 1) * 8 + (tid >> 5);
        const int strd   = (nb - 1) * 8;
        const int target = g_fc1target;
        for (int b = gw; b < 128; b += strd) {
            if (lane == 0) {
                const int* cc = &g_flags.hcnt[b >> 6];
                while (ldacq(cc) < target) __nanosleep(64);
            }
            __syncwarp();
            float acc = 0.f;
            if (lane < 10) {
                acc = fc2_b[lane];
                const float* wp = fc2_w + lane * 200;
                const float* hp = g_flags.hidden + b * 200;
#pragma unroll 5
                for (int h4 = 0; h4 < 50; ++h4) {
                    float4 w  = ((const float4*)wp)[h4];
                    float4 hv = ((const float4*)hp)[h4];
                    float4 fb = ((const float4*)fc1_b)[h4];
                    acc += fmaxf(hv.x + fb.x, 0.f) * w.x + fmaxf(hv.y + fb.y, 0.f) * w.y
                         + fmaxf(hv.z + fb.z, 0.f) * w.z + fmaxf(hv.w + fb.w, 0.f) * w.w;
                }
            }
            float m = (lane < 10) ? acc : -1e30f;
#pragma unroll
            for (int off = 16; off; off >>= 1) m = fmaxf(m, __shfl_xor_sync(0xffffffffu, m, off));
            float e = (lane < 10) ? expf(acc - m) : 0.f;
            float s = e;
#pragma unroll
            for (int off = 16; off; off >>= 1) s += __shfl_xor_sync(0xffffffffu, s, off);
            const float lse = m + logf(s);
            if (lane < 10) out[b * 10 + lane] = acc - lse;
        }
    }
}

// ---------------- launch: ONE memset + ONE kernel ----------------
extern "C" void kernel_launch(void* const* d_in, const int* in_sizes, int n_in,
                              void* d_out, int out_size) {
    const float* x      = (const float*)d_in[0];
    const int*   src    = (const int*)  d_in[1];
    const int*   tgt    = (const int*)  d_in[2];
    const float* conv_w = (const float*)d_in[3];
    const float* conv_b = (const float*)d_in[4];
    const float* fc1_w  = (const float*)d_in[5];
    const float* fc1_b  = (const float*)d_in[6];
    const float* fc2_w  = (const float*)d_in[7];
    const float* fc2_b  = (const float*)d_in[8];

    const int cmax = in_sizes[3] / (NN * 25);
    const int fcK  = in_sizes[5] / 200;

    void* flagsPtr = nullptr;
    cudaGetSymbolAddress(&flagsPtr, g_flags);
    cudaMemsetAsync(flagsPtr, 0, sizeof(Flags), 0);

    int dev = 0, sms = 0, occ = 0;
    cudaGetDevice(&dev);
    cudaDeviceGetAttribute(&sms, cudaDevAttrMultiProcessorCount, dev);
    cudaOccupancyMaxActiveBlocksPerMultiprocessor(&occ, net_kernel, NT, 0);
    int nb = sms * occ;
    if (nb < 129) nb = 129;

    net_kernel<<<nb, NT>>>(x, src, tgt, conv_w, conv_b, fc1_w, fc1_b,
                           fc2_w, fc2_b, (float*)d_out, cmax, fcK, nb);
}

// round 7
// speedup vs baseline: 1.3595x; 1.3595x over previous
#include <cuda_runtime.h>
#include <cuda_bf16.h>
#include <cstdint>

#define NN   256
#define NE   1024
#define MAXC 64
#define WINF (1<<20)
#define NT   256       // threads per block
#define FCP  8         // FC1 k-pieces per input

typedef unsigned long long ull;
union F2U { float2 f; ull u; };

// ---------------- resettable state (ONE memset per replay) ----------------
struct __align__(16) Flags {
    float hidden[128 * 200];   // FC1 atomic accumulators (needs zero)
    int   done[NN * 64];       // (neuron, batch-pair) completion flags
    int   hcnt[2];             // FC1 task counters per 64-batch half
    int   sched_ready;
};
__device__ Flags g_flags;

// ---------------- persistent scratch (rewritten before use) ----------------
__device__ float g_act[(size_t)NN * 128 * 784];   // [n][b][p]
__device__ int   g_fin[NN * MAXC];
__device__ int   g_fcc[NN * MAXC];
__device__ int   g_fdeg[NN];
__device__ int   g_order[NN];
__device__ int   g_ntasks;
__device__ int   g_fc1target;

#define FMA2(d, a, b) \
    asm("fma.rn.f32x2 %0, %1, %2, %0;" : "+l"(d) : "l"(a), "l"(b))

__device__ __forceinline__ int ldacq(const int* p) {
    int v; asm volatile("ld.acquire.gpu.global.b32 %0, [%1];" : "=r"(v) : "l"(p) : "memory");
    return v;
}
__device__ __forceinline__ void strel(int* p, int v) {
    asm volatile("st.release.gpu.global.b32 [%0], %1;" :: "l"(p), "r"(v) : "memory");
}
__device__ __forceinline__ void spinf(const int* p) {        // tight (conv chain)
    if (ldacq(p)) return;
    while (!ldacq(p)) __nanosleep(20);
}
__device__ __forceinline__ void spinb(const int* p) {        // backoff (FC gates)
    if (ldacq(p)) return;
    int d = 256;
    while (!ldacq(p)) { __nanosleep(d); if (d < 4096) d <<= 1; }
}

// ---------------- shared memory union ----------------
struct SchedSM { int src[NE], tgt[NE], wave[NN], need[NN], list[NN]; int chg, cnt; };
struct ConvSM  { ull img[2][1056]; ull wk2[18 * 25]; };
struct FCSM    { float w[16][72]; float2 a[16][66]; };
union  SMU { SchedSM sch; ConvSM cv; FCSM fc; };

// stage one channel (2 batches packed in ull) — conflict-free STS.64
__device__ __forceinline__ void stage2(ull* imgU, const float* sp, int tid) {
    if (tid < 196) {
        const int col  = tid % 28;
        const int rowg = tid / 28;
        const float* p0 = sp + rowg * 4 * 28 + col;
        const float* p1 = p0 + 784;
        ull* d = imgU + (rowg * 4 + 2) * 33 + col + 2;
#pragma unroll
        for (int r = 0; r < 4; ++r) {
            F2U u; u.f = make_float2(__ldg(p0 + r * 28), __ldg(p1 + r * 28));
            d[r * 33] = u.u;
        }
    }
}

// 4px x 2batch packed conv
__device__ __forceinline__ void conv4(const ull* imb, const ull* w2, ull acc[4]) {
#pragma unroll
    for (int dy = 0; dy < 5; ++dy) {
        const ull* rp = imb + dy * 33;
        ull v[8];
#pragma unroll
        for (int j = 0; j < 8; ++j) v[j] = rp[j];
#pragma unroll
        for (int dx = 0; dx < 5; ++dx) {
            ull wv = w2[dy * 5 + dx];
#pragma unroll
            for (int o = 0; o < 4; ++o) FMA2(acc[o], wv, v[dx + o]);
        }
    }
}

__device__ __forceinline__ void store4(ull acc[4], float* d0) {
    F2U u0, u1, u2, u3;
    u0.u = acc[0]; u1.u = acc[1]; u2.u = acc[2]; u3.u = acc[3];
    float4 o0 = make_float4(fmaxf(u0.f.x, 0.f), fmaxf(u1.f.x, 0.f),
                            fmaxf(u2.f.x, 0.f), fmaxf(u3.f.x, 0.f));
    float4 o1 = make_float4(fmaxf(u0.f.y, 0.f), fmaxf(u1.f.y, 0.f),
                            fmaxf(u2.f.y, 0.f), fmaxf(u3.f.y, 0.f));
    *(float4*)d0         = o0;
    *(float4*)(d0 + 784) = o1;
}

// =====================================================================
// single persistent kernel
// =====================================================================
__global__ void __launch_bounds__(NT) net_kernel(
    const float* __restrict__ x,
    const int* __restrict__ src, const int* __restrict__ tgt,
    const float* __restrict__ conv_w, const float* __restrict__ conv_b,
    const float* __restrict__ fc1_w,  const float* __restrict__ fc1_b,
    const float* __restrict__ fc2_w,  const float* __restrict__ fc2_b,
    float* __restrict__ out, int cmax, int fcK, int nb)
{
    __shared__ SMU sm;
    const int tid = threadIdx.x;
    const int bid = blockIdx.x;

    // ================= block 0: scheduler only =================
    if (bid == 0) {
        for (int i = tid; i < NE; i += NT) { sm.sch.src[i] = src[i]; sm.sch.tgt[i] = tgt[i]; }
        for (int i = tid; i < NN; i += NT) { sm.sch.wave[i] = (i == 0) ? 0 : WINF; sm.sch.need[i] = 0; }
        if (tid == 0) { sm.sch.chg = 0; sm.sch.cnt = 0; }
        __syncthreads();

        for (int pass = 0; pass < 300; ++pass) {
            for (int e = tid; e < NE; e += NT) {
                int ws = sm.sch.wave[sm.sch.src[e]];
                if (ws + 1 < sm.sch.wave[sm.sch.tgt[e]]) {
                    atomicMin(&sm.sch.wave[sm.sch.tgt[e]], ws + 1); sm.sch.chg = 1;
                }
            }
            __syncthreads();
            int c = sm.sch.chg; __syncthreads();
            if (tid == 0) sm.sch.chg = 0;
            __syncthreads();
            if (!c) break;
        }

        if (tid == 0) sm.sch.need[255] = 1;
        __syncthreads();
        for (int pass = 0; pass < 300; ++pass) {
            for (int e = tid; e < NE; e += NT) {
                int s = sm.sch.src[e], t = sm.sch.tgt[e];
                if (sm.sch.need[t] && sm.sch.wave[s] < sm.sch.wave[t] && !sm.sch.need[s]) {
                    sm.sch.need[s] = 1; sm.sch.chg = 1;
                }
            }
            __syncthreads();
            int c = sm.sch.chg; __syncthreads();
            if (tid == 0) sm.sch.chg = 0;
            __syncthreads();
            if (!c) break;
        }

        for (int n = tid; n < NN; n += NT) {
            if (n != 0 && n != 255 && sm.sch.need[n]) {
                int r = 0;
                for (int m = 1; m < NN - 1; ++m)
                    if (sm.sch.need[m] && (sm.sch.wave[m] < sm.sch.wave[n] ||
                        (sm.sch.wave[m] == sm.sch.wave[n] && m < n))) r++;
                sm.sch.list[r] = n;
                atomicAdd(&sm.sch.cnt, 1);
            }
        }
        __syncthreads();
        const int total = sm.sch.cnt;

        {   // filtered in-lists via warp ballots (fcc = original channel rank)
            const int w8 = tid >> 5, lane = tid & 31;
            for (int ni = w8; ni <= total; ni += 8) {
                int n  = (ni == total) ? 255 : sm.sch.list[ni];
                int wn = sm.sch.wave[n];
                int cbase = 0, cnt = 0;
                for (int ch = 0; ch < NE; ch += 32) {
                    int e = ch + lane;
                    int te = sm.sch.tgt[e], se = sm.sch.src[e];
                    unsigned m_all  = __ballot_sync(0xffffffffu, te == n);
                    unsigned m_keep = __ballot_sync(0xffffffffu, te == n && sm.sch.wave[se] < wn);
                    if (m_keep & (1u << lane)) {
                        int c   = cbase + __popc(m_all  & ((1u << lane) - 1));
                        int pos = cnt   + __popc(m_keep & ((1u << lane) - 1));
                        if (pos < MAXC) { g_fin[n * MAXC + pos] = se; g_fcc[n * MAXC + pos] = c; }
                    }
                    cbase += __popc(m_all);
                    cnt   += __popc(m_keep);
                }
                if (lane == 0) g_fdeg[n] = cnt < MAXC ? cnt : MAXC;
            }
        }
        __syncthreads();

        // sort each in-list by (input wave, original rank): late producers last
        for (int idx = tid; idx <= total; idx += NT) {
            int n = (idx == total) ? 255 : sm.sch.list[idx];
            int C = g_fdeg[n];
            int* fi = g_fin + n * MAXC;
            int* fo = g_fcc + n * MAXC;
            for (int i = 0; i < C - 1; ++i) {
                int best = i, bk = sm.sch.wave[fi[i]] * 4096 + fo[i];
                for (int j = i + 1; j < C; ++j) {
                    int k = sm.sch.wave[fi[j]] * 4096 + fo[j];
                    if (k < bk) { bk = k; best = j; }
                }
                if (best != i) {
                    int a = fi[i]; fi[i] = fi[best]; fi[best] = a;
                    int b = fo[i]; fo[i] = fo[best]; fo[best] = b;
                }
            }
        }
        for (int i = tid; i < total; i += NT) g_order[i] = sm.sch.list[i];
        __syncthreads();
        if (tid == 0) {
            g_ntasks = total * 64;
            g_fc1target = 4 * g_fdeg[255] * FCP;
            __threadfence();
            strel(&g_flags.sched_ready, 1);
        }
        return;
    }

    // ================= worker blocks =================
    for (int i = tid; i < 2 * 1056; i += NT) ((ull*)sm.cv.img)[i] = 0ull;
    const int yy  = tid / 7;           // valid for tid<196
    const int xx0 = (tid % 7) * 4;
    __syncthreads();

    // ---- wave 0: neuron 0 from x ----
    {
        if (tid < 25) { F2U u; float w = conv_w[tid]; u.f = make_float2(w, w); sm.cv.wk2[tid] = u.u; }
        const float bias = conv_b[0];
        for (int t = bid - 1; t < 64; t += nb - 1) {
            stage2(sm.cv.img[0], x + (size_t)t * 1568, tid);
            __syncthreads();
            if (tid < 196) {
                ull acc[4];
                F2U b2; b2.f = make_float2(bias, bias);
#pragma unroll
                for (int o = 0; o < 4; ++o) acc[o] = b2.u;
                conv4(sm.cv.img[0] + yy * 33 + xx0, sm.cv.wk2, acc);
                store4(acc, g_act + (size_t)(t * 2) * 784 + yy * 28 + xx0);
            }
            __syncthreads();
            if (tid == 0) strel(&g_flags.done[t], 1);
        }
    }

    // ---- wait for schedule (tid0 only) ----
    if (tid == 0) spinf(&g_flags.sched_ready);
    __syncthreads();

    const int ntasks  = g_ntasks;
    const int fdeg255 = g_fdeg[255];

    // ---- dataflow conv tasks (inputs sorted by wave; tid0 JIT gates) ----
    for (int t = bid - 1; t < ntasks; t += nb - 1) {
        const int ni = t >> 6;
        const int pb = t & 63;
        const int n  = g_order[ni];
        const int C  = g_fdeg[n];
        const int* fin = g_fin + n * MAXC;
        const int* fcc = g_fcc + n * MAXC;
        const float* wbase = conv_w + (size_t)n * cmax * 25;

        const int CW = C < 16 ? C : 16;
        for (int i = tid; i < CW * 25; i += NT) {      // weight prefetch (dep-free)
            int c = i / 25, r = i - c * 25;
            F2U u; float w = wbase[fcc[c] * 25 + r];
            u.f = make_float2(w, w);
            sm.cv.wk2[c * 25 + r] = u.u;
        }

        if (tid == 0) spinf(&g_flags.done[fin[0] * 64 + pb]);
        __syncthreads();
        stage2(sm.cv.img[0], g_act + ((size_t)fin[0] * 128 + pb * 2) * 784, tid);
        __syncthreads();

        ull acc[4];
        { F2U b2; float b = conv_b[n]; b2.f = make_float2(b, b);
#pragma unroll
          for (int o = 0; o < 4; ++o) acc[o] = b2.u; }

        for (int c = 0; c < C; ++c) {
            const int buf = c & 1;
            if (c + 1 < C) {
                if (tid == 0) spinf(&g_flags.done[fin[c + 1] * 64 + pb]);
                __syncthreads();
                stage2(sm.cv.img[buf ^ 1],
                       g_act + ((size_t)fin[c + 1] * 128 + pb * 2) * 784, tid);
                if (c + 1 >= 16 && tid < 25) {
                    F2U u; float w = wbase[fcc[c + 1] * 25 + tid];
                    u.f = make_float2(w, w);
                    sm.cv.wk2[(16 + ((c + 1) & 1)) * 25 + tid] = u.u;
                }
            }
            if (tid < 196) {
                const ull* w2 = sm.cv.wk2 + ((c < 16) ? c : (16 + (c & 1))) * 25;
                conv4(sm.cv.img[buf] + yy * 33 + xx0, w2, acc);
            }
            __syncthreads();
        }
        if (tid < 196)
            store4(acc, g_act + ((size_t)n * 128 + pb * 2) * 784 + yy * 28 + xx0);
        __syncthreads();
        if (tid == 0) strel(&g_flags.done[n * 64 + pb], 1);
    }

    // ---- FC1 tasks: (tile[8] x input c x piece) — gated on ONE input ----
    {
        const int ntF = 8 * fdeg255 * FCP;
        const int* fin = g_fin + 255 * MAXC;
        const int* fcc = g_fcc + 255 * MAXC;
        const int hg = tid >> 5;         // 8 groups of 8 h
        const int bg = tid & 31;         // 32 groups of 2 b

        for (int t = bid - 1; t < ntF; t += nb - 1) {
            const int tile = t & 7;
            const int rest = t >> 3;
            const int c    = rest % fdeg255;
            const int pc   = rest / fdeg255;
            const int h0   = (tile >> 1) * 64;
            const int b0   = (tile & 1) * 64;
            const int kq0  = (pc * 49) / FCP;
            const int kq1  = ((pc + 1) * 49) / FCP;

            if (tid < 32) spinb(&g_flags.done[fin[c] * 64 + (b0 >> 1) + tid]);
            __syncthreads();

            ull acc[4][2];
#pragma unroll
            for (int i = 0; i < 4; ++i) { acc[i][0] = 0ull; acc[i][1] = 0ull; }

            const float* wrow0 = fc1_w + (size_t)fcc[c] * 784;
            const float* arow0 = g_act + ((size_t)fin[c] * 128 + b0) * 784;
            const int row = tid >> 2, c4 = tid & 3;

            for (int kq = kq0; kq < kq1; ++kq) {
                const int p0 = kq * 16;
                {   // stage weights 64h x 16k
                    int h = h0 + row;
                    float4 v = (h < 200) ? *(const float4*)(wrow0 + (size_t)h * fcK + p0 + c4 * 4)
                                         : make_float4(0.f, 0.f, 0.f, 0.f);
                    sm.fc.w[c4 * 4 + 0][row] = v.x; sm.fc.w[c4 * 4 + 1][row] = v.y;
                    sm.fc.w[c4 * 4 + 2][row] = v.z; sm.fc.w[c4 * 4 + 3][row] = v.w;
                }
                {   // stage acts 64b x 16k (dup-packed)
                    float4 v = *(const float4*)(arow0 + (size_t)row * 784 + p0 + c4 * 4);
                    sm.fc.a[c4 * 4 + 0][row] = make_float2(v.x, v.x);
                    sm.fc.a[c4 * 4 + 1][row] = make_float2(v.y, v.y);
                    sm.fc.a[c4 * 4 + 2][row] = make_float2(v.z, v.z);
                    sm.fc.a[c4 * 4 + 3][row] = make_float2(v.w, v.w);
                }
                __syncthreads();
#pragma unroll
                for (int k = 0; k < 16; ++k) {
                    const ull* wp = (const ull*)&sm.fc.w[k][hg * 8];
                    const ull* ap = (const ull*)&sm.fc.a[k][bg * 2];
                    ull w0 = wp[0], w1 = wp[1], w2v = wp[2], w3 = wp[3];
                    ull a0 = ap[0], a1 = ap[1];
                    FMA2(acc[0][0], w0,  a0); FMA2(acc[0][1], w0,  a1);
                    FMA2(acc[1][0], w1,  a0); FMA2(acc[1][1], w1,  a1);
                    FMA2(acc[2][0], w2v, a0); FMA2(acc[2][1], w2v, a1);
                    FMA2(acc[3][0], w3,  a0); FMA2(acc[3][1], w3,  a1);
                }
                __syncthreads();
            }
#pragma unroll
            for (int i = 0; i < 4; ++i) {
                const int h = h0 + hg * 8 + i * 2;
                if (h < 200) {
#pragma unroll
                    for (int j = 0; j < 2; ++j) {
                        F2U u; u.u = acc[i][j];
                        const int b = b0 + bg * 2 + j;
                        atomicAdd((float2*)&g_flags.hidden[b * 200 + h], u.f);
                    }
                }
            }
            __syncthreads();
            if (tid == 0) { __threadfence(); atomicAdd(&g_flags.hcnt[b0 >> 6], 1); }
        }
    }

    // ---- FC2 + log_softmax: warp tasks ----
    {
        const int lane   = tid & 31;
        const int gw     = (bid - 1) * 8 + (tid >> 5);
        const int strd   = (nb - 1) * 8;
        const int target = g_fc1target;
        for (int b = gw; b < 128; b += strd) {
            if (lane == 0) {
                const int* cc = &g_flags.hcnt[b >> 6];
                while (ldacq(cc) < target) __nanosleep(512);
            }
            __syncwarp();
            float acc = 0.f;
            if (lane < 10) {
                acc = fc2_b[lane];
                const float* wp = fc2_w + lane * 200;
                const float* hp = g_flags.hidden + b * 200;
#pragma unroll 5
                for (int h4 = 0; h4 < 50; ++h4) {
                    float4 w  = ((const float4*)wp)[h4];
                    float4 hv = ((const float4*)hp)[h4];
                    float4 fb = ((const float4*)fc1_b)[h4];
                    acc += fmaxf(hv.x + fb.x, 0.f) * w.x + fmaxf(hv.y + fb.y, 0.f) * w.y
                         + fmaxf(hv.z + fb.z, 0.f) * w.z + fmaxf(hv.w + fb.w, 0.f) * w.w;
                }
            }
            float m = (lane < 10) ? acc : -1e30f;
#pragma unroll
            for (int off = 16; off; off >>= 1) m = fmaxf(m, __shfl_xor_sync(0xffffffffu, m, off));
            float e = (lane < 10) ? expf(acc - m) : 0.f;
            float s = e;
#pragma unroll
            for (int off = 16; off; off >>= 1) s += __shfl_xor_sync(0xffffffffu, s, off);
            const float lse = m + logf(s);
            if (lane < 10) out[b * 10 + lane] = acc - lse;
        }
    }
}

// ---------------- launch: ONE memset + ONE kernel ----------------
extern "C" void kernel_launch(void* const* d_in, const int* in_sizes, int n_in,
                              void* d_out, int out_size) {
    const float* x      = (const float*)d_in[0];
    const int*   src    = (const int*)  d_in[1];
    const int*   tgt    = (const int*)  d_in[2];
    const float* conv_w = (const float*)d_in[3];
    const float* conv_b = (const float*)d_in[4];
    const float* fc1_w  = (const float*)d_in[5];
    const float* fc1_b  = (const float*)d_in[6];
    const float* fc2_w  = (const float*)d_in[7];
    const float* fc2_b  = (const float*)d_in[8];

    const int cmax = in_sizes[3] / (NN * 25);
    const int fcK  = in_sizes[5] / 200;

    void* flagsPtr = nullptr;
    cudaGetSymbolAddress(&flagsPtr, g_flags);
    cudaMemsetAsync(flagsPtr, 0, sizeof(Flags), 0);

    int dev = 0, sms = 0, occ = 0;
    cudaGetDevice(&dev);
    cudaDeviceGetAttribute(&sms, cudaDevAttrMultiProcessorCount, dev);
    cudaOccupancyMaxActiveBlocksPerMultiprocessor(&occ, net_kernel, NT, 0);
    int nb = sms * occ;
    if (nb < 129) nb = 129;

    net_kernel<<<nb, NT>>>(x, src, tgt, conv_w, conv_b, fc1_w, fc1_b,
                           fc2_w, fc2_b, (float*)d_out, cmax, fcK, nb);
}